// round 13
// baseline (speedup 1.0000x reference)
#include <cuda_runtime.h>
#include <cuda_bf16.h>
#include <cstdint>

// NCEAverage: B=256, D=128, N=1e6, K1=2048, T=0.07, MOMENTUM=0.5
// Output: [ out_l(B*K1) | out_ab(B*K1) | new_memory_l(N*D) | new_memory_ab(N*D) ]
//
// R12 = R11 with the stage-indexing bug fixed: at iteration k we consume
// stage k%4 and refill stage (k+3)%4 (the row consumed at iteration k+3).
// 4-stage cp.async pipeline -> 3 rows outstanding per warp, regs unchanged,
// full occupancy. Unconditional stores; metadata never gates the stream.

#define DIM      128
#define T_INV    (1.0f / 0.07f)
#define N_MAX    1048576
#define CAP      12
#define STAGES   4

__device__ int g_count[N_MAX];
__device__ int g_tasks[N_MAX * CAP];
__device__ int g_ovf  [4096];
__device__ int g_novf;

// ---------------- build: bucket scatter ----------------
__global__ void k_scatter(const int* __restrict__ idx, int bk) {
    for (int t = blockIdx.x * blockDim.x + threadIdx.x; t < bk;
         t += gridDim.x * blockDim.x) {
        const int row  = idx[t];
        const int slot = atomicAdd(&g_count[row], 1);
        if (slot < CAP) g_tasks[row * CAP + slot] = t;
        else            g_ovf[atomicAdd(&g_novf, 1)] = t;
    }
}

// ---------------- cp.async helpers ----------------
__device__ __forceinline__ void cp_async16(uint32_t smem_addr, const void* gptr) {
    asm volatile("cp.async.cg.shared.global [%0], [%1], 16;\n"
                 :: "r"(smem_addr), "l"(gptr) : "memory");
}
__device__ __forceinline__ void cp_commit() {
    asm volatile("cp.async.commit_group;\n" ::: "memory");
}
__device__ __forceinline__ void cp_wait2() {
    asm volatile("cp.async.wait_group 2;\n" ::: "memory");
}

// ---------------- streaming pass: copy + score, smem-pipelined --------------
__global__ void __launch_bounds__(256) stream_score(
    const float4* __restrict__ bank, float4* __restrict__ outb,
    const float4* __restrict__ query, float* __restrict__ out_score,
    int Nrows, int K1)
{
    __shared__ float4 buf[STAGES * 256];          // 16 KB: 4 stages x 8 warps x 512B

    const int lane = threadIdx.x & 31;
    const int w    = threadIdx.x >> 5;
    const int nw   = gridDim.x * 8;               // total warps
    const int wid  = blockIdx.x * 8 + w;

    // per-lane smem address of stage-0 slot
    const uint32_t sbase =
        (uint32_t)__cvta_generic_to_shared(&buf[w * 32 + lane]);

    // prologue: fill stages 0..2 with rows wid, wid+nw, wid+2nw
    #pragma unroll
    for (int s = 0; s < STAGES - 1; ++s) {
        const long long rr = (long long)wid + (long long)s * nw;
        if (rr < Nrows)
            cp_async16(sbase + (uint32_t)s * 256 * 16, &bank[rr * 32 + lane]);
        cp_commit();
    }

    int s = 0;
    for (long long r = wid; r < Nrows; r += nw) {
        cp_wait2();                               // stage s data has landed
        const float4 v = buf[s * 256 + w * 32 + lane];

        __stcs(&outb[r * 32 + lane], v);          // unconditional copy

        int cnt = g_count[r];
        if (cnt) {
            if (cnt > CAP) cnt = CAP;
            const int base = (int)r * CAP;
            for (int j = 0; j < cnt; ++j) {
                const int task = g_tasks[base + j];
                const int b    = task / K1;
                const float4 q = query[b * 32 + lane];
                float sc = v.x * q.x + v.y * q.y + v.z * q.z + v.w * q.w;
                #pragma unroll
                for (int o = 16; o; o >>= 1)
                    sc += __shfl_xor_sync(0xffffffffu, sc, o);
                if (lane == 0) out_score[task] = sc * T_INV;
            }
        }

        // refill the stage that iteration k+3 will consume: (s+3) & 3
        const long long rp = r + (long long)(STAGES - 1) * nw;
        if (rp < Nrows)
            cp_async16(sbase + (uint32_t)((s + STAGES - 1) & (STAGES - 1)) * 256 * 16,
                       &bank[rp * 32 + lane]);
        cp_commit();
        s = (s + 1) & (STAGES - 1);
    }
}

// ---------------- update (+ overflow fixup in block B) ----------------
__global__ void __launch_bounds__(DIM) update_kernel(
    const float* __restrict__ l, const float* __restrict__ ab,
    const int* __restrict__ y, const int* __restrict__ idx,
    const float* __restrict__ mem_l, const float* __restrict__ mem_ab,
    float* __restrict__ out_l, float* __restrict__ out_ab,
    float* __restrict__ out_ml, float* __restrict__ out_mab, int B, int K1)
{
    const int tid = threadIdx.x;

    if (blockIdx.x == (unsigned)B) {
        const int n = g_novf;                     // expected 0
        const int lane = tid & 31;
        for (int i = tid >> 5; i < n; i += 4) {
            const int task = g_ovf[i];
            const int b    = task / K1;
            const long long row = idx[task];
            const float4 wl  = ((const float4*)(mem_l  + row * DIM))[lane];
            const float4 wab = ((const float4*)(mem_ab + row * DIM))[lane];
            const float4 q1  = ((const float4*)ab)[b * 32 + lane];
            const float4 q2  = ((const float4*)l )[b * 32 + lane];
            float s1 = wl.x * q1.x + wl.y * q1.y + wl.z * q1.z + wl.w * q1.w;
            float s2 = wab.x * q2.x + wab.y * q2.y + wab.z * q2.z + wab.w * q2.w;
            #pragma unroll
            for (int o = 16; o; o >>= 1) {
                s1 += __shfl_xor_sync(0xffffffffu, s1, o);
                s2 += __shfl_xor_sync(0xffffffffu, s2, o);
            }
            if (lane == 0) {
                out_ab[task] = s1 * T_INV;
                out_l [task] = s2 * T_INV;
            }
        }
        return;
    }

    const int b = blockIdx.x;
    __shared__ int skip;
    __shared__ int yy_s;
    if (tid == 0) { skip = 0; yy_s = y[b]; }
    __syncthreads();
    const int yy = yy_s;
    for (int j = b + 1 + tid; j < B; j += DIM)
        if (y[j] == yy) skip = 1;                 // benign race
    __syncthreads();
    if (skip) return;

    const long long r = yy;
    const float vl  = 0.5f * mem_l [r * DIM + tid] + 0.5f * l [b * DIM + tid];
    const float vab = 0.5f * mem_ab[r * DIM + tid] + 0.5f * ab[b * DIM + tid];

    float sl = vl * vl, sab = vab * vab;
    #pragma unroll
    for (int off = 16; off; off >>= 1) {
        sl  += __shfl_xor_sync(0xffffffffu, sl,  off);
        sab += __shfl_xor_sync(0xffffffffu, sab, off);
    }
    __shared__ float wsl[4], wsab[4];
    const int w = tid >> 5, lane = tid & 31;
    if (lane == 0) { wsl[w] = sl; wsab[w] = sab; }
    __syncthreads();
    const float tsl  = wsl[0]  + wsl[1]  + wsl[2]  + wsl[3];
    const float tsab = wsab[0] + wsab[1] + wsab[2] + wsab[3];

    out_ml [r * DIM + tid] = vl  * rsqrtf(tsl);
    out_mab[r * DIM + tid] = vab * rsqrtf(tsab);
}

extern "C" void kernel_launch(void* const* d_in, const int* in_sizes, int n_in,
                              void* d_out, int out_size)
{
    const float* l      = (const float*)d_in[0];
    const float* ab     = (const float*)d_in[1];
    const int*   y      = (const int*)  d_in[2];
    const int*   idx    = (const int*)  d_in[3];
    const float* mem_l  = (const float*)d_in[4];
    const float* mem_ab = (const float*)d_in[5];

    const int       B     = in_sizes[2];
    const int       BK    = in_sizes[3];
    const int       K1    = BK / B;
    const long long ND    = (long long)in_sizes[4];
    const int       Nrows = (int)(ND / DIM);

    float* out = (float*)d_out;
    float* out_l   = out;
    float* out_ab  = out + BK;
    float* out_ml  = out + 2LL * BK;
    float* out_mab = out + 2LL * BK + ND;

    // ---- reset metadata (no allocation; graph-capturable) ----
    void* p_count; cudaGetSymbolAddress(&p_count, g_count);
    void* p_novf;  cudaGetSymbolAddress(&p_novf,  g_novf);
    cudaMemsetAsync(p_count, 0, (size_t)Nrows * sizeof(int));
    cudaMemsetAsync(p_novf,  0, sizeof(int));

    // ---- build: row->task buckets ----
    k_scatter<<<512, 1024>>>(idx, BK);

    // ---- pass 1: bank_l -> out_ml, score vs ab -> out_ab ----
    stream_score<<<148 * 8, 256>>>((const float4*)mem_l, (float4*)out_ml,
                                   (const float4*)ab, out_ab, Nrows, K1);

    // ---- pass 2: bank_ab -> out_mab, score vs l -> out_l ----
    stream_score<<<148 * 8, 256>>>((const float4*)mem_ab, (float4*)out_mab,
                                   (const float4*)l, out_l, Nrows, K1);

    // ---- row updates + overflow fixup ----
    update_kernel<<<B + 1, DIM>>>(l, ab, y, idx, mem_l, mem_ab,
                                  out_l, out_ab, out_ml, out_mab, B, K1);
}

// round 14
// speedup vs baseline: 1.2171x; 1.2171x over previous
#include <cuda_runtime.h>
#include <cuda_bf16.h>
#include <cstdint>

// NCEAverage: B=256, D=128, N=1e6, K1=2048, T=0.07, MOMENTUM=0.5
// Output: [ out_l(B*K1) | out_ab(B*K1) | new_memory_l(N*D) | new_memory_ab(N*D) ]
//
// R14 = R9 (best) + register-free L2 prefetch at distance 2*nw in the stream
// loop + overflow fixup folded into the update kernel. Nothing else touched:
// unconditional stores, register prefetch at distance nw, bucket build.

#define DIM      128
#define T_INV    (1.0f / 0.07f)
#define N_MAX    1048576
#define CAP      12

__device__ int g_count[N_MAX];
__device__ int g_tasks[N_MAX * CAP];
__device__ int g_ovf  [4096];
__device__ int g_novf;

// ---------------- build: bucket scatter ----------------
__global__ void k_scatter(const int* __restrict__ idx, int bk) {
    for (int t = blockIdx.x * blockDim.x + threadIdx.x; t < bk;
         t += gridDim.x * blockDim.x) {
        const int row  = idx[t];
        const int slot = atomicAdd(&g_count[row], 1);
        if (slot < CAP) g_tasks[row * CAP + slot] = t;
        else            g_ovf[atomicAdd(&g_novf, 1)] = t;
    }
}

// ---------------- streaming pass: copy + score ----------------
// One warp per row. Register prefetch at distance nw; L2 prefetch at 2*nw
// so the register load hits L2 instead of DRAM. Store depends only on v.
__global__ void __launch_bounds__(256) stream_score(
    const float4* __restrict__ bank, float4* __restrict__ outb,
    const float4* __restrict__ query, float* __restrict__ out_score,
    int Nrows, int K1)
{
    const int lane = threadIdx.x & 31;
    const int nw   = gridDim.x * (blockDim.x >> 5);
    int r          = blockIdx.x * (blockDim.x >> 5) + (threadIdx.x >> 5);

    if (r >= Nrows) return;
    float4 v   = __ldcs(&bank[(long long)r * 32 + lane]);
    int    cnt = g_count[r];

    while (true) {
        const int rn = r + nw;
        const int rp = r + 2 * nw;
        if (rp < Nrows)                           // register-free L2 prefetch
            asm volatile("prefetch.global.L2 [%0];"
                         :: "l"(&bank[(long long)rp * 32 + lane]));

        float4 vn;
        int    cn = 0;
        if (rn < Nrows) {                         // register prefetch (from L2)
            vn = __ldcs(&bank[(long long)rn * 32 + lane]);
            cn = g_count[rn];
        }

        __stcs(&outb[(long long)r * 32 + lane], v);   // unconditional copy

        if (cnt) {
            if (cnt > CAP) cnt = CAP;
            const int base = r * CAP;
            for (int j = 0; j < cnt; ++j) {
                const int task = g_tasks[base + j];
                const int b    = task / K1;
                const float4 q = query[b * 32 + lane];
                float s = v.x * q.x + v.y * q.y + v.z * q.z + v.w * q.w;
                #pragma unroll
                for (int o = 16; o; o >>= 1) s += __shfl_xor_sync(0xffffffffu, s, o);
                if (lane == 0) out_score[task] = s * T_INV;
            }
        }
        if (rn >= Nrows) break;
        r   = rn;
        v   = vn;
        cnt = cn;
    }
}

// ---------------- update (+ overflow fixup in block B) ----------------
__global__ void __launch_bounds__(DIM) update_kernel(
    const float* __restrict__ l, const float* __restrict__ ab,
    const int* __restrict__ y, const int* __restrict__ idx,
    const float* __restrict__ mem_l, const float* __restrict__ mem_ab,
    float* __restrict__ out_l, float* __restrict__ out_ab,
    float* __restrict__ out_ml, float* __restrict__ out_mab, int B, int K1)
{
    const int tid = threadIdx.x;

    if (blockIdx.x == (unsigned)B) {
        const int n = g_novf;                     // expected 0
        const int lane = tid & 31;
        for (int i = tid >> 5; i < n; i += 4) {
            const int task = g_ovf[i];
            const int b    = task / K1;
            const long long row = idx[task];
            const float4 wl  = ((const float4*)(mem_l  + row * DIM))[lane];
            const float4 wab = ((const float4*)(mem_ab + row * DIM))[lane];
            const float4 q1  = ((const float4*)ab)[b * 32 + lane];
            const float4 q2  = ((const float4*)l )[b * 32 + lane];
            float s1 = wl.x * q1.x + wl.y * q1.y + wl.z * q1.z + wl.w * q1.w;
            float s2 = wab.x * q2.x + wab.y * q2.y + wab.z * q2.z + wab.w * q2.w;
            #pragma unroll
            for (int o = 16; o; o >>= 1) {
                s1 += __shfl_xor_sync(0xffffffffu, s1, o);
                s2 += __shfl_xor_sync(0xffffffffu, s2, o);
            }
            if (lane == 0) {
                out_ab[task] = s1 * T_INV;
                out_l [task] = s2 * T_INV;
            }
        }
        return;
    }

    const int b = blockIdx.x;
    __shared__ int skip;
    __shared__ int yy_s;
    if (tid == 0) { skip = 0; yy_s = y[b]; }
    __syncthreads();
    const int yy = yy_s;
    for (int j = b + 1 + tid; j < B; j += DIM)
        if (y[j] == yy) skip = 1;                 // benign race
    __syncthreads();
    if (skip) return;

    const long long r = yy;
    const float vl  = 0.5f * mem_l [r * DIM + tid] + 0.5f * l [b * DIM + tid];
    const float vab = 0.5f * mem_ab[r * DIM + tid] + 0.5f * ab[b * DIM + tid];

    float sl = vl * vl, sab = vab * vab;
    #pragma unroll
    for (int off = 16; off; off >>= 1) {
        sl  += __shfl_xor_sync(0xffffffffu, sl,  off);
        sab += __shfl_xor_sync(0xffffffffu, sab, off);
    }
    __shared__ float wsl[4], wsab[4];
    const int w = tid >> 5, lane = tid & 31;
    if (lane == 0) { wsl[w] = sl; wsab[w] = sab; }
    __syncthreads();
    const float tsl  = wsl[0]  + wsl[1]  + wsl[2]  + wsl[3];
    const float tsab = wsab[0] + wsab[1] + wsab[2] + wsab[3];

    out_ml [r * DIM + tid] = vl  * rsqrtf(tsl);
    out_mab[r * DIM + tid] = vab * rsqrtf(tsab);
}

extern "C" void kernel_launch(void* const* d_in, const int* in_sizes, int n_in,
                              void* d_out, int out_size)
{
    const float* l      = (const float*)d_in[0];
    const float* ab     = (const float*)d_in[1];
    const int*   y      = (const int*)  d_in[2];
    const int*   idx    = (const int*)  d_in[3];
    const float* mem_l  = (const float*)d_in[4];
    const float* mem_ab = (const float*)d_in[5];

    const int       B     = in_sizes[2];
    const int       BK    = in_sizes[3];
    const int       K1    = BK / B;
    const long long ND    = (long long)in_sizes[4];
    const int       Nrows = (int)(ND / DIM);

    float* out = (float*)d_out;
    float* out_l   = out;
    float* out_ab  = out + BK;
    float* out_ml  = out + 2LL * BK;
    float* out_mab = out + 2LL * BK + ND;

    // ---- reset metadata (no allocation; graph-capturable) ----
    void* p_count; cudaGetSymbolAddress(&p_count, g_count);
    void* p_novf;  cudaGetSymbolAddress(&p_novf,  g_novf);
    cudaMemsetAsync(p_count, 0, (size_t)Nrows * sizeof(int));
    cudaMemsetAsync(p_novf,  0, sizeof(int));

    // ---- build: row->task buckets ----
    k_scatter<<<512, 1024>>>(idx, BK);

    // ---- pass 1: bank_l -> out_ml, score vs ab -> out_ab ----
    stream_score<<<148 * 8, 256>>>((const float4*)mem_l, (float4*)out_ml,
                                   (const float4*)ab, out_ab, Nrows, K1);

    // ---- pass 2: bank_ab -> out_mab, score vs l -> out_l ----
    stream_score<<<148 * 8, 256>>>((const float4*)mem_ab, (float4*)out_mab,
                                   (const float4*)l, out_l, Nrows, K1);

    // ---- row updates + overflow fixup ----
    update_kernel<<<B + 1, DIM>>>(l, ab, y, idx, mem_l, mem_ab,
                                  out_l, out_ab, out_ml, out_mab, B, K1);
}

// round 15
// speedup vs baseline: 1.2995x; 1.0677x over previous
#include <cuda_runtime.h>
#include <cuda_bf16.h>
#include <cstdint>

// NCEAverage: B=256, D=128, N=1e6, K1=2048, T=0.07, MOMENTUM=0.5
// Output: [ out_l(B*K1) | out_ab(B*K1) | new_memory_l(N*D) | new_memory_ab(N*D) ]
//
// R15 = R9 loop body untouched (the proven-optimal stream), but both bank
// passes fused into ONE kernel via block-range split: blocks [0,G/2) stream
// bank_l, blocks [G/2,G) stream bank_ab. One launch, overlapped drain tails.
// Overflow fixup folded into the update kernel.

#define DIM      128
#define T_INV    (1.0f / 0.07f)
#define N_MAX    1048576
#define CAP      12

__device__ int g_count[N_MAX];
__device__ int g_tasks[N_MAX * CAP];
__device__ int g_ovf  [4096];
__device__ int g_novf;

// ---------------- build: bucket scatter ----------------
__global__ void k_scatter(const int* __restrict__ idx, int bk) {
    for (int t = blockIdx.x * blockDim.x + threadIdx.x; t < bk;
         t += gridDim.x * blockDim.x) {
        const int row  = idx[t];
        const int slot = atomicAdd(&g_count[row], 1);
        if (slot < CAP) g_tasks[row * CAP + slot] = t;
        else            g_ovf[atomicAdd(&g_novf, 1)] = t;
    }
}

// ---------------- dual streaming pass: copy + score ----------------
// Block halves pick their bank; per-half loop is EXACTLY the R9 stream:
// one warp per row, register prefetch at distance nw, unconditional store.
__global__ void __launch_bounds__(256) stream_score_dual(
    const float4* __restrict__ bank_l, const float4* __restrict__ bank_ab,
    float4* __restrict__ out_ml, float4* __restrict__ out_mab,
    const float4* __restrict__ ql, const float4* __restrict__ qab,
    float* __restrict__ out_l, float* __restrict__ out_ab,
    int Nrows, int K1)
{
    const int halfG = gridDim.x >> 1;
    const bool second = (blockIdx.x >= (unsigned)halfG);
    const int  blk    = second ? (blockIdx.x - halfG) : blockIdx.x;

    const float4* __restrict__ bank  = second ? bank_ab : bank_l;
    float4*       __restrict__ outb  = second ? out_mab : out_ml;
    const float4* __restrict__ query = second ? ql      : qab;
    float*        __restrict__ out_s = second ? out_l   : out_ab;

    const int lane = threadIdx.x & 31;
    const int nw   = halfG * (blockDim.x >> 5);
    int r          = blk * (blockDim.x >> 5) + (threadIdx.x >> 5);

    if (r >= Nrows) return;
    float4 v   = __ldcs(&bank[(long long)r * 32 + lane]);
    int    cnt = g_count[r];

    while (true) {
        const int rn = r + nw;
        float4 vn;
        int    cn = 0;
        if (rn < Nrows) {                         // prefetch next row + count
            vn = __ldcs(&bank[(long long)rn * 32 + lane]);
            cn = g_count[rn];
        }

        __stcs(&outb[(long long)r * 32 + lane], v);   // unconditional copy

        if (cnt) {
            if (cnt > CAP) cnt = CAP;
            const int base = r * CAP;
            for (int j = 0; j < cnt; ++j) {
                const int task = g_tasks[base + j];
                const int b    = task / K1;
                const float4 q = query[b * 32 + lane];
                float s = v.x * q.x + v.y * q.y + v.z * q.z + v.w * q.w;
                #pragma unroll
                for (int o = 16; o; o >>= 1) s += __shfl_xor_sync(0xffffffffu, s, o);
                if (lane == 0) out_s[task] = s * T_INV;
            }
        }
        if (rn >= Nrows) break;
        r   = rn;
        v   = vn;
        cnt = cn;
    }
}

// ---------------- update (+ overflow fixup in block B) ----------------
__global__ void __launch_bounds__(DIM) update_kernel(
    const float* __restrict__ l, const float* __restrict__ ab,
    const int* __restrict__ y, const int* __restrict__ idx,
    const float* __restrict__ mem_l, const float* __restrict__ mem_ab,
    float* __restrict__ out_l, float* __restrict__ out_ab,
    float* __restrict__ out_ml, float* __restrict__ out_mab, int B, int K1)
{
    const int tid = threadIdx.x;

    if (blockIdx.x == (unsigned)B) {
        const int n = g_novf;                     // expected 0
        const int lane = tid & 31;
        for (int i = tid >> 5; i < n; i += 4) {
            const int task = g_ovf[i];
            const int b    = task / K1;
            const long long row = idx[task];
            const float4 wl  = ((const float4*)(mem_l  + row * DIM))[lane];
            const float4 wab = ((const float4*)(mem_ab + row * DIM))[lane];
            const float4 q1  = ((const float4*)ab)[b * 32 + lane];
            const float4 q2  = ((const float4*)l )[b * 32 + lane];
            float s1 = wl.x * q1.x + wl.y * q1.y + wl.z * q1.z + wl.w * q1.w;
            float s2 = wab.x * q2.x + wab.y * q2.y + wab.z * q2.z + wab.w * q2.w;
            #pragma unroll
            for (int o = 16; o; o >>= 1) {
                s1 += __shfl_xor_sync(0xffffffffu, s1, o);
                s2 += __shfl_xor_sync(0xffffffffu, s2, o);
            }
            if (lane == 0) {
                out_ab[task] = s1 * T_INV;
                out_l [task] = s2 * T_INV;
            }
        }
        return;
    }

    const int b = blockIdx.x;
    __shared__ int skip;
    __shared__ int yy_s;
    if (tid == 0) { skip = 0; yy_s = y[b]; }
    __syncthreads();
    const int yy = yy_s;
    for (int j = b + 1 + tid; j < B; j += DIM)
        if (y[j] == yy) skip = 1;                 // benign race
    __syncthreads();
    if (skip) return;

    const long long r = yy;
    const float vl  = 0.5f * mem_l [r * DIM + tid] + 0.5f * l [b * DIM + tid];
    const float vab = 0.5f * mem_ab[r * DIM + tid] + 0.5f * ab[b * DIM + tid];

    float sl = vl * vl, sab = vab * vab;
    #pragma unroll
    for (int off = 16; off; off >>= 1) {
        sl  += __shfl_xor_sync(0xffffffffu, sl,  off);
        sab += __shfl_xor_sync(0xffffffffu, sab, off);
    }
    __shared__ float wsl[4], wsab[4];
    const int w = tid >> 5, lane = tid & 31;
    if (lane == 0) { wsl[w] = sl; wsab[w] = sab; }
    __syncthreads();
    const float tsl  = wsl[0]  + wsl[1]  + wsl[2]  + wsl[3];
    const float tsab = wsab[0] + wsab[1] + wsab[2] + wsab[3];

    out_ml [r * DIM + tid] = vl  * rsqrtf(tsl);
    out_mab[r * DIM + tid] = vab * rsqrtf(tsab);
}

extern "C" void kernel_launch(void* const* d_in, const int* in_sizes, int n_in,
                              void* d_out, int out_size)
{
    const float* l      = (const float*)d_in[0];
    const float* ab     = (const float*)d_in[1];
    const int*   y      = (const int*)  d_in[2];
    const int*   idx    = (const int*)  d_in[3];
    const float* mem_l  = (const float*)d_in[4];
    const float* mem_ab = (const float*)d_in[5];

    const int       B     = in_sizes[2];
    const int       BK    = in_sizes[3];
    const int       K1    = BK / B;
    const long long ND    = (long long)in_sizes[4];
    const int       Nrows = (int)(ND / DIM);

    float* out = (float*)d_out;
    float* out_l   = out;
    float* out_ab  = out + BK;
    float* out_ml  = out + 2LL * BK;
    float* out_mab = out + 2LL * BK + ND;

    // ---- reset metadata (no allocation; graph-capturable) ----
    void* p_count; cudaGetSymbolAddress(&p_count, g_count);
    void* p_novf;  cudaGetSymbolAddress(&p_novf,  g_novf);
    cudaMemsetAsync(p_count, 0, (size_t)Nrows * sizeof(int));
    cudaMemsetAsync(p_novf,  0, sizeof(int));

    // ---- build: row->task buckets ----
    k_scatter<<<512, 1024>>>(idx, BK);

    // ---- single fused pass: both banks streamed by block halves ----
    stream_score_dual<<<148 * 8 * 2, 256>>>(
        (const float4*)mem_l, (const float4*)mem_ab,
        (float4*)out_ml, (float4*)out_mab,
        (const float4*)l, (const float4*)ab,
        out_l, out_ab, Nrows, K1);

    // ---- row updates + overflow fixup ----
    update_kernel<<<B + 1, DIM>>>(l, ab, y, idx, mem_l, mem_ab,
                                  out_l, out_ab, out_ml, out_mab, B, K1);
}